// round 8
// baseline (speedup 1.0000x reference)
#include <cuda_runtime.h>
#include <cuda_fp16.h>
#include <math.h>
#include <cstdint>

#define BB 256
#define TT 512
#define DD 256
#define HH 64
#define KTAG 32
#define GH 192      // 3*H
#define NCOMB 384   // fw 192 | bw 192

// Scratch (allocation-free rule: __device__ globals)
__device__ float g_xp[(size_t)BB * TT * NCOMB];      // [b,t, fw(z,r,h)|bw(z,r,h)]
__device__ float g_hidden[(size_t)BB * TT * 2 * HH]; // [b,t, fw64|bw64]
// fp16x2 planes of X [131072][256] and combined transposed weights [384][256]
__device__ unsigned short g_Xh0[(size_t)BB * TT * DD];
__device__ unsigned short g_Xh1[(size_t)BB * TT * DD];
__device__ unsigned short g_Bh0[(size_t)NCOMB * DD];
__device__ unsigned short g_Bh1[(size_t)NCOMB * DD];

// packed fp32x2 helpers
#define FFMA2(acc, a, b) \
    asm("fma.rn.f32x2 %0, %1, %2, %0;" : "+l"(acc) : "l"(a), "l"(b))
#define PACK2(out, lo, hi) \
    asm("mov.b64 %0, {%1, %2};" : "=l"(out) : "r"(__float_as_uint(lo)), "r"(__float_as_uint(hi)))
#define UNPACK2(lo, hi, in) \
    asm("mov.b64 {%0, %1}, %2;" : "=f"(lo), "=f"(hi) : "l"(in))

// fast gate math: MUFU ex2/rcp only, no IEEE div, rel err ~1e-6
__device__ __forceinline__ float fast_sigmoid(float x) {
    float e, r;
    asm("ex2.approx.ftz.f32 %0, %1;" : "=f"(e) : "f"(x * -1.4426950408889634f));
    asm("rcp.approx.ftz.f32 %0, %1;" : "=f"(r) : "f"(1.0f + e));
    return r;
}
__device__ __forceinline__ float fast_tanh(float x) {
    float ax = fabsf(x);
    float e, r;
    asm("ex2.approx.ftz.f32 %0, %1;" : "=f"(e) : "f"(ax * -2.8853900817779268f));
    asm("rcp.approx.ftz.f32 %0, %1;" : "=f"(r) : "f"(1.0f + e));
    float t = (1.0f - e) * r;
    return __uint_as_float(__float_as_uint(t) | (__float_as_uint(x) & 0x80000000u));
}

// fp16 mma m16n8k16 (native HMMA, sm_80+, valid under compute_103)
#define MMA_F16(c, a, b) \
    asm volatile("mma.sync.aligned.m16n8k16.row.col.f32.f16.f16.f32 " \
        "{%0,%1,%2,%3}, {%4,%5,%6,%7}, {%8,%9}, {%0,%1,%2,%3};" \
        : "+f"((c)[0]), "+f"((c)[1]), "+f"((c)[2]), "+f"((c)[3]) \
        : "r"((a)[0]), "r"((a)[1]), "r"((a)[2]), "r"((a)[3]), \
          "r"((b)[0]), "r"((b)[1]))

__device__ __forceinline__ void fp16_split2(float x, unsigned short& h0, unsigned short& h1)
{
    __half a = __float2half_rn(x);
    float f0 = __half2float(a);
    __half b = __float2half_rn(x - f0);
    h0 = __half_as_ushort(a);
    h1 = __half_as_ushort(b);
}

// ---------------------------------------------------------------------------
// K0a: split X into 2 fp16 planes (memory-bound)
// ---------------------------------------------------------------------------
__global__ void prep_x(const float* __restrict__ X)
{
    const size_t N4 = (size_t)BB * TT * DD / 4;
    size_t i = (size_t)blockIdx.x * blockDim.x + threadIdx.x;
    size_t stride = (size_t)gridDim.x * blockDim.x;
    for (size_t p = i; p < N4; p += stride) {
        float4 v = ((const float4*)X)[p];
        float xs[4] = {v.x, v.y, v.z, v.w};
        unsigned short h0[4], h1[4];
#pragma unroll
        for (int e = 0; e < 4; e++) fp16_split2(xs[e], h0[e], h1[e]);
        ((uint2*)g_Xh0)[p] = make_uint2((uint32_t)h0[0] | ((uint32_t)h0[1] << 16),
                                        (uint32_t)h0[2] | ((uint32_t)h0[3] << 16));
        ((uint2*)g_Xh1)[p] = make_uint2((uint32_t)h1[0] | ((uint32_t)h1[1] << 16),
                                        (uint32_t)h1[2] | ((uint32_t)h1[3] << 16));
    }
}

// ---------------------------------------------------------------------------
// K0b: transpose + split the combined input weights: g_Bh[n][k]
// ---------------------------------------------------------------------------
__global__ void prep_b(const float* __restrict__ fwK, const float* __restrict__ bwK)
{
    int n = blockIdx.x;     // 0..383
    int k = threadIdx.x;    // 0..255
    float w = (n < GH) ? fwK[(size_t)k * GH + n] : bwK[(size_t)k * GH + (n - GH)];
    unsigned short h0, h1;
    fp16_split2(w, h0, h1);
    g_Bh0[(size_t)n * DD + k] = h0;
    g_Bh1[(size_t)n * DD + k] = h1;
}

// ---------------------------------------------------------------------------
// K1: proj = X @ Bt^T + bias via fp16x2 3-product mma.sync m16n8k16 (unchanged)
// ---------------------------------------------------------------------------
#define PITCH 20
#define APLANE 2560   // u32 units per plane (128 rows * 20)
#define SM_BIAS 0
#define SM_A 512
#define SM_B (512 + 2 * APLANE * 4)
#define SMEM_PROJ (512 + 4 * APLANE * 4)   // 41472 bytes

__global__ __launch_bounds__(256) void proj_mma(
    const float* __restrict__ fwB, const float* __restrict__ bwB)
{
    extern __shared__ __align__(16) char smem[];
    float* bias_sm = (float*)(smem + SM_BIAS);
    uint32_t* AU = (uint32_t*)(smem + SM_A);
    uint32_t* BU = (uint32_t*)(smem + SM_B);

    const int tid = threadIdx.x;
    const int w = tid >> 5;
    const int lane = tid & 31;
    const int g = lane >> 2;
    const int x = lane & 3;
    const int m_off = (w & 1) * 64;
    const int n_off = (w >> 1) * 32;

    const int n0 = blockIdx.x * 128;   // 0,128,256
    const int m0 = blockIdx.y * 128;

    for (int i = tid; i < 128; i += 256) {
        int n = n0 + i;
        bias_sm[i] = (n < GH) ? fwB[n] : bwB[n - GH];
    }

    float C[4][4][4];
#pragma unroll
    for (int mt = 0; mt < 4; mt++)
#pragma unroll
        for (int nt = 0; nt < 4; nt++)
#pragma unroll
            for (int q = 0; q < 4; q++) C[mt][nt][q] = 0.f;

    int ar0[4], bc0[4];
#pragma unroll
    for (int mt = 0; mt < 4; mt++) ar0[mt] = (m_off + mt * 16 + g) * PITCH;
#pragma unroll
    for (int nt = 0; nt < 4; nt++) bc0[nt] = (n_off + nt * 8 + g) * PITCH;

    const unsigned short* Asrc[2] = {g_Xh0, g_Xh1};
    const unsigned short* Bsrc[2] = {g_Bh0, g_Bh1};

    const int crow = tid >> 2;    // 0..63
    const int cq = tid & 3;       // 0..3

    for (int ks = 0; ks < 8; ks++) {
        const int k0 = ks * 32;
#pragma unroll
        for (int p = 0; p < 2; p++) {
#pragma unroll
            for (int rep = 0; rep < 2; rep++) {
                int r = crow + rep * 64;
                uint4 va = *(const uint4*)(Asrc[p] + (size_t)(m0 + r) * DD + k0 + cq * 8);
                *(uint4*)(AU + p * APLANE + r * PITCH + cq * 4) = va;
                uint4 vb = *(const uint4*)(Bsrc[p] + (size_t)(n0 + r) * DD + k0 + cq * 8);
                *(uint4*)(BU + p * APLANE + r * PITCH + cq * 4) = vb;
            }
        }
        __syncthreads();

#pragma unroll
        for (int s = 0; s < 2; s++) {
            const int ub = s * 8 + x;
            uint32_t bf[2][4][2];
#pragma unroll
            for (int p = 0; p < 2; p++)
#pragma unroll
                for (int nt = 0; nt < 4; nt++) {
                    bf[p][nt][0] = BU[p * APLANE + bc0[nt] + ub];
                    bf[p][nt][1] = BU[p * APLANE + bc0[nt] + ub + 4];
                }
#pragma unroll
            for (int pa = 0; pa < 2; pa++) {
                uint32_t af[4][4];
#pragma unroll
                for (int mt = 0; mt < 4; mt++) {
                    int base = pa * APLANE + ar0[mt] + ub;
                    af[mt][0] = AU[base];
                    af[mt][1] = AU[base + 8 * PITCH];
                    af[mt][2] = AU[base + 4];
                    af[mt][3] = AU[base + 8 * PITCH + 4];
                }
                const int nbp = 2 - pa;
#pragma unroll
                for (int pb = 0; pb < 2; pb++) {
                    if (pb >= nbp) break;
#pragma unroll
                    for (int mt = 0; mt < 4; mt++)
#pragma unroll
                        for (int nt = 0; nt < 4; nt++)
                            MMA_F16(C[mt][nt], af[mt], bf[pb][nt]);
                }
            }
        }
        __syncthreads();
    }

#pragma unroll
    for (int mt = 0; mt < 4; mt++) {
        int r0 = m0 + m_off + mt * 16 + g;
#pragma unroll
        for (int nt = 0; nt < 4; nt++) {
            int col = n_off + nt * 8 + 2 * x;
            float b0 = bias_sm[col], b1 = bias_sm[col + 1];
            float2 v0 = make_float2(C[mt][nt][0] + b0, C[mt][nt][1] + b1);
            float2 v1 = make_float2(C[mt][nt][2] + b0, C[mt][nt][3] + b1);
            *(float2*)(g_xp + (size_t)r0 * NCOMB + n0 + col) = v0;
            *(float2*)(g_xp + (size_t)(r0 + 8) * NCOMB + n0 + col) = v1;
        }
    }
}

// ---------------------------------------------------------------------------
// K2: GRU recurrence. NBAT=4 batches/block (128 blocks, single wave).
// Threads 0..63: gate consumers (4 batches each, ILP). Threads 64..191:
// producers, each owns (batch pid>>5, cols pc & pc+32), 3-stage reg pipeline.
// Matvec by all 192 threads with LDS.128 h loads + FFMA2.
// ---------------------------------------------------------------------------
#define NBAT 4
#define RS 4

__global__ __launch_bounds__(192) void gru_kernel(
    const float* __restrict__ rec_fw, const float* __restrict__ rec_bw,
    const float* __restrict__ bias_fw, const float* __restrict__ bias_bw,
    const int* __restrict__ mask)
{
    __shared__ __align__(16) float h_sm[NBAT][HH];
    __shared__ float hp_sm[NBAT][GH];
    __shared__ float ring[RS][NBAT][3][HH];
    __shared__ int ringm[RS][NBAT];

    const int dir = blockIdx.y;
    const int b0 = blockIdx.x * NBAT;
    const int j = threadIdx.x;

    const float* rec = dir ? rec_bw : rec_fw;
    unsigned long long rp[HH / 2];
#pragma unroll
    for (int i = 0; i < HH / 2; i++) {
        float r0 = rec[(2 * i) * GH + j];
        float r1 = rec[(2 * i + 1) * GH + j];
        PACK2(rp[i], r0, r1);
    }
    const float brj = (dir ? bias_bw : bias_fw)[GH + j];

    if (j < HH) {
#pragma unroll
        for (int nb = 0; nb < NBAT; nb++) h_sm[nb][j] = 0.f;
    }

    // producer identity (threads 64..191): batch pnb, columns pc and pc+32
    const int pid = j - HH;
    const int pnb = (pid >> 5) & 3;
    const int pc = pid & 31;

    float s[3][6];
    int sm[3];
#pragma unroll
    for (int q = 0; q < 3; q++) { sm[q] = 1;
#pragma unroll
        for (int e = 0; e < 6; e++) s[q][e] = 0.f; }

#define LDXP(TF, SI) do { \
        int _tt = dir ? (TT - 1 - (TF)) : (TF); \
        const float* _xr = g_xp + ((size_t)(b0 + pnb) * TT + _tt) * NCOMB + dir * GH; \
        s[SI][0] = _xr[pc];          s[SI][1] = _xr[pc + 32]; \
        s[SI][2] = _xr[HH + pc];     s[SI][3] = _xr[HH + pc + 32]; \
        s[SI][4] = _xr[2 * HH + pc]; s[SI][5] = _xr[2 * HH + pc + 32]; \
        if (pc == 0) sm[SI] = mask[(b0 + pnb) * TT + _tt]; \
    } while (0)

    if (j >= HH) {
        for (int f = 0; f < 3; f++) {
            LDXP(f, 0);
            ring[f][pnb][0][pc] = s[0][0]; ring[f][pnb][0][pc + 32] = s[0][1];
            ring[f][pnb][1][pc] = s[0][2]; ring[f][pnb][1][pc + 32] = s[0][3];
            ring[f][pnb][2][pc] = s[0][4]; ring[f][pnb][2][pc + 32] = s[0][5];
            if (pc == 0) ringm[f][pnb] = sm[0];
        }
        LDXP(3, 0);
        LDXP(4, 1);
        LDXP(5, 2);
    }
    __syncthreads();

    int sr = 0;   // consumer slot (step t)
    int sw = 3;   // producer STS slot (step t+3)

    const ulonglong2* h40 = (const ulonglong2*)h_sm[0];
    const ulonglong2* h41 = (const ulonglong2*)h_sm[1];
    const ulonglong2* h42 = (const ulonglong2*)h_sm[2];
    const ulonglong2* h43 = (const ulonglong2*)h_sm[3];

    for (int t = 0; t < TT; t++) {
        // matvec: all 192 threads, 4 batches, LDS.128 h loads
        unsigned long long a0x = 0ULL, a0y = 0ULL, a1x = 0ULL, a1y = 0ULL;
        unsigned long long a2x = 0ULL, a2y = 0ULL, a3x = 0ULL, a3y = 0ULL;
#pragma unroll
        for (int i = 0; i < 16; i++) {
            ulonglong2 v0 = h40[i];
            ulonglong2 v1 = h41[i];
            ulonglong2 v2 = h42[i];
            ulonglong2 v3 = h43[i];
            FFMA2(a0x, rp[2 * i], v0.x); FFMA2(a0y, rp[2 * i + 1], v0.y);
            FFMA2(a1x, rp[2 * i], v1.x); FFMA2(a1y, rp[2 * i + 1], v1.y);
            FFMA2(a2x, rp[2 * i], v2.x); FFMA2(a2y, rp[2 * i + 1], v2.y);
            FFMA2(a3x, rp[2 * i], v3.x); FFMA2(a3y, rp[2 * i + 1], v3.y);
        }
        {
            float x0, x1, y0, y1;
            UNPACK2(x0, x1, a0x); UNPACK2(y0, y1, a0y);
            hp_sm[0][j] = (x0 + x1) + (y0 + y1) + brj;
            UNPACK2(x0, x1, a1x); UNPACK2(y0, y1, a1y);
            hp_sm[1][j] = (x0 + x1) + (y0 + y1) + brj;
            UNPACK2(x0, x1, a2x); UNPACK2(y0, y1, a2y);
            hp_sm[2][j] = (x0 + x1) + (y0 + y1) + brj;
            UNPACK2(x0, x1, a3x); UNPACK2(y0, y1, a3y);
            hp_sm[3][j] = (x0 + x1) + (y0 + y1) + brj;
        }
        __syncthreads();

        if (j < HH) {
            const int tt = dir ? (TT - 1 - t) : t;
#pragma unroll
            for (int nb = 0; nb < NBAT; nb++) {
                float xz = ring[sr][nb][0][j];
                float xr_ = ring[sr][nb][1][j];
                float xh = ring[sr][nb][2][j];
                int m = ringm[sr][nb];
                float hz = hp_sm[nb][j];
                float hr = hp_sm[nb][HH + j];
                float hc = hp_sm[nb][2 * HH + j];
                float hprev = h_sm[nb][j];
                float z = fast_sigmoid(xz + hz);
                float r = fast_sigmoid(xr_ + hr);
                float c = fast_tanh(xh + r * hc);
                float hn = z * hprev + (1.f - z) * c;
                if (m <= 0) hn = hprev;
                h_sm[nb][j] = hn;
                g_hidden[((size_t)(b0 + nb) * TT + tt) * (2 * HH) + dir * HH + j] = hn;
            }
        } else {
            const int tf = t + 3;
            if (tf < TT) {
                ring[sw][pnb][0][pc] = s[0][0]; ring[sw][pnb][0][pc + 32] = s[0][1];
                ring[sw][pnb][1][pc] = s[0][2]; ring[sw][pnb][1][pc + 32] = s[0][3];
                ring[sw][pnb][2][pc] = s[0][4]; ring[sw][pnb][2][pc + 32] = s[0][5];
                if (pc == 0) ringm[sw][pnb] = sm[0];
            }
#pragma unroll
            for (int e = 0; e < 6; e++) { s[0][e] = s[1][e]; s[1][e] = s[2][e]; }
            sm[0] = sm[1]; sm[1] = sm[2];
            const int tl = t + 6;
            if (tl < TT) LDXP(tl, 2);
        }
        __syncthreads();

        sr++; if (sr == RS) sr = 0;
        sw++; if (sw == RS) sw = 0;
    }
#undef LDXP
}

// ---------------------------------------------------------------------------
// K3: potentials. 16 rows/block; warp w computes rows 2w,2w+1 with FFMA2
// against duplicated-packed dense columns (ds2). Broadcast row loads.
// ---------------------------------------------------------------------------
#define PROWS 16

__global__ __launch_bounds__(256) void pot_kernel(
    const float* __restrict__ dk, const float* __restrict__ db,
    const float* __restrict__ lb, const float* __restrict__ rb,
    float* __restrict__ pot)
{
    __shared__ __align__(16) unsigned long long ds2[2 * HH][KTAG]; // 32KB
    __shared__ __align__(16) float rows_i[2 * HH][PROWS];          // 8KB

    const int tid = threadIdx.x;

    for (int i = tid; i < 2 * HH * KTAG; i += 256) {
        float v = dk[i];
        int h = i >> 5, k = i & 31;
        unsigned long long d;
        PACK2(d, v, v);
        ds2[h][k] = d;
    }

    const size_t row0 = (size_t)blockIdx.x * PROWS;
    {
        int r = tid & 15, hb = (tid >> 4) * 8;
        const float* src = g_hidden + (row0 + r) * (2 * HH) + hb;
        float4 v0 = ((const float4*)src)[0];
        float4 v1 = ((const float4*)src)[1];
        rows_i[hb + 0][r] = v0.x; rows_i[hb + 1][r] = v0.y;
        rows_i[hb + 2][r] = v0.z; rows_i[hb + 3][r] = v0.w;
        rows_i[hb + 4][r] = v1.x; rows_i[hb + 5][r] = v1.y;
        rows_i[hb + 6][r] = v1.z; rows_i[hb + 7][r] = v1.w;
    }
    __syncthreads();

    const int w = tid >> 5, lane = tid & 31;
    float bv = db[lane];
    unsigned long long acc;
    PACK2(acc, bv, bv);
#pragma unroll
    for (int h = 0; h < 2 * HH; h++) {
        unsigned long long hv = *(const unsigned long long*)&rows_i[h][2 * w];
        FFMA2(acc, hv, ds2[h][lane]);
    }
    float o0, o1;
    UNPACK2(o0, o1, acc);

    size_t ra = row0 + 2 * w;
    size_t rb_ = ra + 1;
    int ta = (int)(ra % TT), tb = (int)(rb_ % TT);
    if (ta == 0)      o0 += lb[lane];
    if (ta == TT - 1) o0 += rb[lane];
    if (tb == 0)      o1 += lb[lane];
    if (tb == TT - 1) o1 += rb[lane];
    pot[ra * KTAG + lane] = o0;
    pot[rb_ * KTAG + lane] = o1;
}

// ---------------------------------------------------------------------------
// K4: Viterbi (unchanged)
// ---------------------------------------------------------------------------
__device__ __forceinline__ void amerge(float& mv, int& mi, float v, int i)
{
    if (v > mv || (v == mv && i < mi)) { mv = v; mi = i; }
}

__global__ __launch_bounds__(32) void viterbi_kernel(
    const float* __restrict__ pot, const float* __restrict__ trans,
    const int* __restrict__ mask,
    float* __restrict__ out_dec, float* __restrict__ out_len)
{
    __shared__ unsigned char bp[TT][KTAG];
    __shared__ unsigned char dec[TT];

    int b = blockIdx.x, k = threadIdx.x;

    float tr[KTAG];
#pragma unroll
    for (int j = 0; j < KTAG; j++) tr[j] = trans[j * KTAG + k];

    const float* pb = pot + (size_t)b * TT * KTAG;
    float s = pb[k];

    for (int t0 = 1; t0 < TT; t0 += 8) {
        float pv[8];
#pragma unroll
        for (int u = 0; u < 8; u++) {
            int t = t0 + u;
            pv[u] = (t < TT) ? pb[(size_t)t * KTAG + k] : 0.f;
        }
#pragma unroll
        for (int u = 0; u < 8; u++) {
            int t = t0 + u;
            if (t >= TT) break;
            float m0 = -INFINITY, m1 = -INFINITY, m2 = -INFINITY, m3 = -INFINITY;
            int i0 = 0, i1 = 1, i2 = 2, i3 = 3;
#pragma unroll
            for (int j = 0; j < KTAG; j += 4) {
                float v0 = __shfl_sync(0xffffffffu, s, j)     + tr[j];
                float v1 = __shfl_sync(0xffffffffu, s, j + 1) + tr[j + 1];
                float v2 = __shfl_sync(0xffffffffu, s, j + 2) + tr[j + 2];
                float v3 = __shfl_sync(0xffffffffu, s, j + 3) + tr[j + 3];
                if (v0 > m0) { m0 = v0; i0 = j; }
                if (v1 > m1) { m1 = v1; i1 = j + 1; }
                if (v2 > m2) { m2 = v2; i2 = j + 2; }
                if (v3 > m3) { m3 = v3; i3 = j + 3; }
            }
            amerge(m0, i0, m1, i1);
            amerge(m2, i2, m3, i3);
            amerge(m0, i0, m2, i2);
            s = m0 + pv[u];
            bp[t][k] = (unsigned char)i0;
        }
    }

    float m0 = -INFINITY, m1 = -INFINITY, m2 = -INFINITY, m3 = -INFINITY;
    int i0 = 0, i1 = 1, i2 = 2, i3 = 3;
#pragma unroll
    for (int j = 0; j < KTAG; j += 4) {
        float v0 = __shfl_sync(0xffffffffu, s, j);
        float v1 = __shfl_sync(0xffffffffu, s, j + 1);
        float v2 = __shfl_sync(0xffffffffu, s, j + 2);
        float v3 = __shfl_sync(0xffffffffu, s, j + 3);
        if (v0 > m0) { m0 = v0; i0 = j; }
        if (v1 > m1) { m1 = v1; i1 = j + 1; }
        if (v2 > m2) { m2 = v2; i2 = j + 2; }
        if (v3 > m3) { m3 = v3; i3 = j + 3; }
    }
    amerge(m0, i0, m1, i1);
    amerge(m2, i2, m3, i3);
    amerge(m0, i0, m2, i2);

    __syncwarp();
    if (k == 0) {
        int tag = i0;
        dec[TT - 1] = (unsigned char)tag;
        for (int t = TT - 2; t >= 0; t--) {
            tag = bp[t + 1][tag];
            dec[t] = (unsigned char)tag;
        }
    }
    __syncwarp();

    for (int t = k; t < TT; t += 32)
        out_dec[(size_t)b * TT + t] = (float)dec[t];

    int sum = 0;
    for (int t = k; t < TT; t += 32) sum += mask[(size_t)b * TT + t];
#pragma unroll
    for (int o = 16; o > 0; o >>= 1) sum += __shfl_down_sync(0xffffffffu, sum, o);
    if (k == 0) out_len[b] = (float)sum;
}

// K5: copy chain_kernel into the output tail
__global__ void tail_kernel(const float* __restrict__ chain, float* __restrict__ outc)
{
    int i = threadIdx.x + blockIdx.x * blockDim.x;
    if (i < KTAG * KTAG) outc[i] = chain[i];
}

// ---------------------------------------------------------------------------
extern "C" void kernel_launch(void* const* d_in, const int* in_sizes, int n_in,
                              void* d_out, int out_size)
{
    const float* X      = (const float*)d_in[0];
    const int*   mask   = (const int*)d_in[1];
    const float* fwK    = (const float*)d_in[2];
    const float* fwR    = (const float*)d_in[3];
    const float* fwBias = (const float*)d_in[4];
    const float* bwK    = (const float*)d_in[5];
    const float* bwR    = (const float*)d_in[6];
    const float* bwBias = (const float*)d_in[7];
    const float* dK     = (const float*)d_in[8];
    const float* dB     = (const float*)d_in[9];
    const float* chain  = (const float*)d_in[10];
    const float* lb     = (const float*)d_in[11];
    const float* rb     = (const float*)d_in[12];

    float* out       = (float*)d_out;
    float* out_dec   = out;                              // B*T
    float* pot       = out + (size_t)BB * TT;            // B*T*K
    float* out_len   = pot + (size_t)BB * TT * KTAG;     // B
    float* out_chain = out_len + BB;                     // K*K

    cudaFuncSetAttribute(proj_mma, cudaFuncAttributeMaxDynamicSharedMemorySize, SMEM_PROJ);

    prep_x<<<2048, 256>>>(X);
    prep_b<<<NCOMB, 256>>>(fwK, bwK);
    dim3 gp(NCOMB / 128, (BB * TT) / 128);
    proj_mma<<<gp, 256, SMEM_PROJ>>>(fwBias, bwBias);
    dim3 g2(BB / NBAT, 2);
    gru_kernel<<<g2, GH>>>(fwR, bwR, fwBias, bwBias, mask);   // 4th launch -> ncu
    pot_kernel<<<(BB * TT) / PROWS, 256>>>(dK, dB, lb, rb, pot);
    viterbi_kernel<<<BB, 32>>>(pot, chain, mask, out_dec, out_len);
    tail_kernel<<<4, 256>>>(chain, out_chain);
}

// round 9
// speedup vs baseline: 1.1540x; 1.1540x over previous
#include <cuda_runtime.h>
#include <cuda_fp16.h>
#include <math.h>
#include <cstdint>

#define BB 256
#define TT 512
#define DD 256
#define HH 64
#define KTAG 32
#define GH 192      // 3*H
#define NCOMB 384   // fw 192 | bw 192

// Scratch (allocation-free rule: __device__ globals)
__device__ float g_xp[(size_t)BB * TT * NCOMB];      // [b,t, fw(z,r,h)|bw(z,r,h)]
__device__ float g_hidden[(size_t)BB * TT * 2 * HH]; // [b,t, fw64|bw64]
// fp16x2 planes of X [131072][256] and combined transposed weights [384][256]
__device__ unsigned short g_Xh0[(size_t)BB * TT * DD];
__device__ unsigned short g_Xh1[(size_t)BB * TT * DD];
__device__ unsigned short g_Bh0[(size_t)NCOMB * DD];
__device__ unsigned short g_Bh1[(size_t)NCOMB * DD];

// packed fp32x2 helpers
#define FFMA2(acc, a, b) \
    asm("fma.rn.f32x2 %0, %1, %2, %0;" : "+l"(acc) : "l"(a), "l"(b))
#define PACK2(out, lo, hi) \
    asm("mov.b64 %0, {%1, %2};" : "=l"(out) : "r"(__float_as_uint(lo)), "r"(__float_as_uint(hi)))
#define UNPACK2(lo, hi, in) \
    asm("mov.b64 {%0, %1}, %2;" : "=f"(lo), "=f"(hi) : "l"(in))

// fast gate math: MUFU ex2/rcp only, no IEEE div, rel err ~1e-6
__device__ __forceinline__ float fast_sigmoid(float x) {
    float e, r;
    asm("ex2.approx.ftz.f32 %0, %1;" : "=f"(e) : "f"(x * -1.4426950408889634f));
    asm("rcp.approx.ftz.f32 %0, %1;" : "=f"(r) : "f"(1.0f + e));
    return r;
}
__device__ __forceinline__ float fast_tanh(float x) {
    float ax = fabsf(x);
    float e, r;
    asm("ex2.approx.ftz.f32 %0, %1;" : "=f"(e) : "f"(ax * -2.8853900817779268f));
    asm("rcp.approx.ftz.f32 %0, %1;" : "=f"(r) : "f"(1.0f + e));
    float t = (1.0f - e) * r;
    return __uint_as_float(__float_as_uint(t) | (__float_as_uint(x) & 0x80000000u));
}

// fp16 mma m16n8k16 (native HMMA, sm_80+, valid under compute_103)
#define MMA_F16(c, a, b) \
    asm volatile("mma.sync.aligned.m16n8k16.row.col.f32.f16.f16.f32 " \
        "{%0,%1,%2,%3}, {%4,%5,%6,%7}, {%8,%9}, {%0,%1,%2,%3};" \
        : "+f"((c)[0]), "+f"((c)[1]), "+f"((c)[2]), "+f"((c)[3]) \
        : "r"((a)[0]), "r"((a)[1]), "r"((a)[2]), "r"((a)[3]), \
          "r"((b)[0]), "r"((b)[1]))

__device__ __forceinline__ void fp16_split2(float x, unsigned short& h0, unsigned short& h1)
{
    __half a = __float2half_rn(x);
    float f0 = __half2float(a);
    __half b = __float2half_rn(x - f0);
    h0 = __half_as_ushort(a);
    h1 = __half_as_ushort(b);
}

// ---------------------------------------------------------------------------
// K0a: split X into 2 fp16 planes (memory-bound)
// ---------------------------------------------------------------------------
__global__ void prep_x(const float* __restrict__ X)
{
    const size_t N4 = (size_t)BB * TT * DD / 4;
    size_t i = (size_t)blockIdx.x * blockDim.x + threadIdx.x;
    size_t stride = (size_t)gridDim.x * blockDim.x;
    for (size_t p = i; p < N4; p += stride) {
        float4 v = ((const float4*)X)[p];
        float xs[4] = {v.x, v.y, v.z, v.w};
        unsigned short h0[4], h1[4];
#pragma unroll
        for (int e = 0; e < 4; e++) fp16_split2(xs[e], h0[e], h1[e]);
        ((uint2*)g_Xh0)[p] = make_uint2((uint32_t)h0[0] | ((uint32_t)h0[1] << 16),
                                        (uint32_t)h0[2] | ((uint32_t)h0[3] << 16));
        ((uint2*)g_Xh1)[p] = make_uint2((uint32_t)h1[0] | ((uint32_t)h1[1] << 16),
                                        (uint32_t)h1[2] | ((uint32_t)h1[3] << 16));
    }
}

// ---------------------------------------------------------------------------
// K0b: transpose + split the combined input weights: g_Bh[n][k]
// ---------------------------------------------------------------------------
__global__ void prep_b(const float* __restrict__ fwK, const float* __restrict__ bwK)
{
    int n = blockIdx.x;     // 0..383
    int k = threadIdx.x;    // 0..255
    float w = (n < GH) ? fwK[(size_t)k * GH + n] : bwK[(size_t)k * GH + (n - GH)];
    unsigned short h0, h1;
    fp16_split2(w, h0, h1);
    g_Bh0[(size_t)n * DD + k] = h0;
    g_Bh1[(size_t)n * DD + k] = h1;
}

// ---------------------------------------------------------------------------
// K1: proj = X @ Bt^T + bias via fp16x2 3-product mma.sync m16n8k16 (unchanged)
// ---------------------------------------------------------------------------
#define PITCH 20
#define APLANE 2560   // u32 units per plane (128 rows * 20)
#define SM_BIAS 0
#define SM_A 512
#define SM_B (512 + 2 * APLANE * 4)
#define SMEM_PROJ (512 + 4 * APLANE * 4)   // 41472 bytes

__global__ __launch_bounds__(256) void proj_mma(
    const float* __restrict__ fwB, const float* __restrict__ bwB)
{
    extern __shared__ __align__(16) char smem[];
    float* bias_sm = (float*)(smem + SM_BIAS);
    uint32_t* AU = (uint32_t*)(smem + SM_A);
    uint32_t* BU = (uint32_t*)(smem + SM_B);

    const int tid = threadIdx.x;
    const int w = tid >> 5;
    const int lane = tid & 31;
    const int g = lane >> 2;
    const int x = lane & 3;
    const int m_off = (w & 1) * 64;
    const int n_off = (w >> 1) * 32;

    const int n0 = blockIdx.x * 128;   // 0,128,256
    const int m0 = blockIdx.y * 128;

    for (int i = tid; i < 128; i += 256) {
        int n = n0 + i;
        bias_sm[i] = (n < GH) ? fwB[n] : bwB[n - GH];
    }

    float C[4][4][4];
#pragma unroll
    for (int mt = 0; mt < 4; mt++)
#pragma unroll
        for (int nt = 0; nt < 4; nt++)
#pragma unroll
            for (int q = 0; q < 4; q++) C[mt][nt][q] = 0.f;

    int ar0[4], bc0[4];
#pragma unroll
    for (int mt = 0; mt < 4; mt++) ar0[mt] = (m_off + mt * 16 + g) * PITCH;
#pragma unroll
    for (int nt = 0; nt < 4; nt++) bc0[nt] = (n_off + nt * 8 + g) * PITCH;

    const unsigned short* Asrc[2] = {g_Xh0, g_Xh1};
    const unsigned short* Bsrc[2] = {g_Bh0, g_Bh1};

    const int crow = tid >> 2;    // 0..63
    const int cq = tid & 3;       // 0..3

    for (int ks = 0; ks < 8; ks++) {
        const int k0 = ks * 32;
#pragma unroll
        for (int p = 0; p < 2; p++) {
#pragma unroll
            for (int rep = 0; rep < 2; rep++) {
                int r = crow + rep * 64;
                uint4 va = *(const uint4*)(Asrc[p] + (size_t)(m0 + r) * DD + k0 + cq * 8);
                *(uint4*)(AU + p * APLANE + r * PITCH + cq * 4) = va;
                uint4 vb = *(const uint4*)(Bsrc[p] + (size_t)(n0 + r) * DD + k0 + cq * 8);
                *(uint4*)(BU + p * APLANE + r * PITCH + cq * 4) = vb;
            }
        }
        __syncthreads();

#pragma unroll
        for (int s = 0; s < 2; s++) {
            const int ub = s * 8 + x;
            uint32_t bf[2][4][2];
#pragma unroll
            for (int p = 0; p < 2; p++)
#pragma unroll
                for (int nt = 0; nt < 4; nt++) {
                    bf[p][nt][0] = BU[p * APLANE + bc0[nt] + ub];
                    bf[p][nt][1] = BU[p * APLANE + bc0[nt] + ub + 4];
                }
#pragma unroll
            for (int pa = 0; pa < 2; pa++) {
                uint32_t af[4][4];
#pragma unroll
                for (int mt = 0; mt < 4; mt++) {
                    int base = pa * APLANE + ar0[mt] + ub;
                    af[mt][0] = AU[base];
                    af[mt][1] = AU[base + 8 * PITCH];
                    af[mt][2] = AU[base + 4];
                    af[mt][3] = AU[base + 8 * PITCH + 4];
                }
                const int nbp = 2 - pa;
#pragma unroll
                for (int pb = 0; pb < 2; pb++) {
                    if (pb >= nbp) break;
#pragma unroll
                    for (int mt = 0; mt < 4; mt++)
#pragma unroll
                        for (int nt = 0; nt < 4; nt++)
                            MMA_F16(C[mt][nt], af[mt], bf[pb][nt]);
                }
            }
        }
        __syncthreads();
    }

#pragma unroll
    for (int mt = 0; mt < 4; mt++) {
        int r0 = m0 + m_off + mt * 16 + g;
#pragma unroll
        for (int nt = 0; nt < 4; nt++) {
            int col = n_off + nt * 8 + 2 * x;
            float b0 = bias_sm[col], b1 = bias_sm[col + 1];
            float2 v0 = make_float2(C[mt][nt][0] + b0, C[mt][nt][1] + b1);
            float2 v1 = make_float2(C[mt][nt][2] + b0, C[mt][nt][3] + b1);
            *(float2*)(g_xp + (size_t)r0 * NCOMB + n0 + col) = v0;
            *(float2*)(g_xp + (size_t)(r0 + 8) * NCOMB + n0 + col) = v1;
        }
    }
}

// ---------------------------------------------------------------------------
// K2: GRU recurrence — R7 structure (NBAT=2, 256 blocks, warp-specialized
// deep prefetch) with LDS.128 h loads in the matvec.
// ---------------------------------------------------------------------------
#define NBAT 2
#define RS 4

__global__ __launch_bounds__(192) void gru_kernel(
    const float* __restrict__ rec_fw, const float* __restrict__ rec_bw,
    const float* __restrict__ bias_fw, const float* __restrict__ bias_bw,
    const int* __restrict__ mask)
{
    __shared__ __align__(16) float h_sm[NBAT][HH];
    __shared__ float hp_sm[NBAT][GH];
    __shared__ float ring[RS][NBAT][3][HH];
    __shared__ int ringm[RS][NBAT];

    const int dir = blockIdx.y;
    const int b0 = blockIdx.x * NBAT;
    const int j = threadIdx.x;

    const float* rec = dir ? rec_bw : rec_fw;
    unsigned long long rp[HH / 2];
#pragma unroll
    for (int i = 0; i < HH / 2; i++) {
        float r0 = rec[(2 * i) * GH + j];
        float r1 = rec[(2 * i + 1) * GH + j];
        PACK2(rp[i], r0, r1);
    }
    const float brj = (dir ? bias_bw : bias_fw)[GH + j];

    if (j < HH) {
#pragma unroll
        for (int nb = 0; nb < NBAT; nb++) h_sm[nb][j] = 0.f;
    }

    // producer identity (threads 64..191)
    const int pid = j - HH;          // 0..127 when producer
    const int pnb = (pid >> 6) & 1;  // batch 0/1
    const int pjj = pid & 63;

#define LDXP(TF, Z, R, H, M) do { \
        int _ttf = dir ? (TT - 1 - (TF)) : (TF); \
        const float* _xr = g_xp + ((size_t)(b0 + pnb) * TT + _ttf) * NCOMB + dir * GH; \
        Z = _xr[pjj]; R = _xr[HH + pjj]; H = _xr[2 * HH + pjj]; \
        M = mask[(b0 + pnb) * TT + _ttf]; \
    } while (0)

    float s0z = 0, s0r = 0, s0h = 0, s1z = 0, s1r = 0, s1h = 0, s2z = 0, s2r = 0, s2h = 0;
    int s0m = 1, s1m = 1, s2m = 1;

    if (j >= HH) {
        for (int f = 0; f < 3; f++) {
            float z, r, h; int m;
            LDXP(f, z, r, h, m);
            ring[f][pnb][0][pjj] = z;
            ring[f][pnb][1][pjj] = r;
            ring[f][pnb][2][pjj] = h;
            if (pjj == 0) ringm[f][pnb] = m;
        }
        LDXP(3, s0z, s0r, s0h, s0m);
        LDXP(4, s1z, s1r, s1h, s1m);
        LDXP(5, s2z, s2r, s2h, s2m);
    }
    __syncthreads();

    int sr = 0;   // consumer slot (step t)
    int sw = 3;   // producer STS slot (step t+3)

    const ulonglong2* h40 = (const ulonglong2*)h_sm[0];
    const ulonglong2* h41 = (const ulonglong2*)h_sm[1];

    for (int t = 0; t < TT; t++) {
        // matvec: all 192 threads, LDS.128 h loads, 4 FFMA2 chains
        unsigned long long a0x = 0ULL, a0y = 0ULL, a1x = 0ULL, a1y = 0ULL;
#pragma unroll
        for (int i = 0; i < 16; i++) {
            ulonglong2 v0 = h40[i];
            ulonglong2 v1 = h41[i];
            FFMA2(a0x, rp[2 * i], v0.x); FFMA2(a0y, rp[2 * i + 1], v0.y);
            FFMA2(a1x, rp[2 * i], v1.x); FFMA2(a1y, rp[2 * i + 1], v1.y);
        }
        {
            float x0, x1, y0, y1;
            UNPACK2(x0, x1, a0x); UNPACK2(y0, y1, a0y);
            hp_sm[0][j] = (x0 + x1) + (y0 + y1) + brj;
            UNPACK2(x0, x1, a1x); UNPACK2(y0, y1, a1y);
            hp_sm[1][j] = (x0 + x1) + (y0 + y1) + brj;
        }
        __syncthreads();

        if (j < HH) {
            const int tt = dir ? (TT - 1 - t) : t;
#pragma unroll
            for (int nb = 0; nb < NBAT; nb++) {
                float xz = ring[sr][nb][0][j];
                float xr_ = ring[sr][nb][1][j];
                float xh = ring[sr][nb][2][j];
                int m = ringm[sr][nb];
                float hz = hp_sm[nb][j];
                float hr = hp_sm[nb][HH + j];
                float hc = hp_sm[nb][2 * HH + j];
                float hprev = h_sm[nb][j];
                float z = fast_sigmoid(xz + hz);
                float r = fast_sigmoid(xr_ + hr);
                float c = fast_tanh(xh + r * hc);
                float hn = z * hprev + (1.f - z) * c;
                if (m <= 0) hn = hprev;
                h_sm[nb][j] = hn;
                g_hidden[((size_t)(b0 + nb) * TT + tt) * (2 * HH) + dir * HH + j] = hn;
            }
        } else {
            const int tf = t + 3;
            if (tf < TT) {
                ring[sw][pnb][0][pjj] = s0z;
                ring[sw][pnb][1][pjj] = s0r;
                ring[sw][pnb][2][pjj] = s0h;
                if (pjj == 0) ringm[sw][pnb] = s0m;
            }
            s0z = s1z; s0r = s1r; s0h = s1h; s0m = s1m;
            s1z = s2z; s1r = s2r; s1h = s2h; s1m = s2m;
            const int tl = t + 6;
            if (tl < TT) LDXP(tl, s2z, s2r, s2h, s2m);
        }
        __syncthreads();

        sr++; if (sr == RS) sr = 0;
        sw++; if (sw == RS) sw = 0;
    }
#undef LDXP
}

// ---------------------------------------------------------------------------
// K3: potentials. 16 rows/block; warp w computes rows 2w,2w+1 with FFMA2
// against duplicated-packed dense columns (ds2). Broadcast row loads.
// ---------------------------------------------------------------------------
#define PROWS 16

__global__ __launch_bounds__(256) void pot_kernel(
    const float* __restrict__ dk, const float* __restrict__ db,
    const float* __restrict__ lb, const float* __restrict__ rb,
    float* __restrict__ pot)
{
    __shared__ __align__(16) unsigned long long ds2[2 * HH][KTAG]; // 32KB
    __shared__ __align__(16) float rows_i[2 * HH][PROWS];          // 8KB

    const int tid = threadIdx.x;

    for (int i = tid; i < 2 * HH * KTAG; i += 256) {
        float v = dk[i];
        int h = i >> 5, k = i & 31;
        unsigned long long d;
        PACK2(d, v, v);
        ds2[h][k] = d;
    }

    const size_t row0 = (size_t)blockIdx.x * PROWS;
    {
        int r = tid & 15, hb = (tid >> 4) * 8;
        const float* src = g_hidden + (row0 + r) * (2 * HH) + hb;
        float4 v0 = ((const float4*)src)[0];
        float4 v1 = ((const float4*)src)[1];
        rows_i[hb + 0][r] = v0.x; rows_i[hb + 1][r] = v0.y;
        rows_i[hb + 2][r] = v0.z; rows_i[hb + 3][r] = v0.w;
        rows_i[hb + 4][r] = v1.x; rows_i[hb + 5][r] = v1.y;
        rows_i[hb + 6][r] = v1.z; rows_i[hb + 7][r] = v1.w;
    }
    __syncthreads();

    const int w = tid >> 5, lane = tid & 31;
    float bv = db[lane];
    unsigned long long acc;
    PACK2(acc, bv, bv);
#pragma unroll
    for (int h = 0; h < 2 * HH; h++) {
        unsigned long long hv = *(const unsigned long long*)&rows_i[h][2 * w];
        FFMA2(acc, hv, ds2[h][lane]);
    }
    float o0, o1;
    UNPACK2(o0, o1, acc);

    size_t ra = row0 + 2 * w;
    size_t rb_ = ra + 1;
    int ta = (int)(ra % TT), tb = (int)(rb_ % TT);
    if (ta == 0)      o0 += lb[lane];
    if (ta == TT - 1) o0 += rb[lane];
    if (tb == 0)      o1 += lb[lane];
    if (tb == TT - 1) o1 += rb[lane];
    pot[ra * KTAG + lane] = o0;
    pot[rb_ * KTAG + lane] = o1;
}

// ---------------------------------------------------------------------------
// K4: Viterbi (unchanged)
// ---------------------------------------------------------------------------
__device__ __forceinline__ void amerge(float& mv, int& mi, float v, int i)
{
    if (v > mv || (v == mv && i < mi)) { mv = v; mi = i; }
}

__global__ __launch_bounds__(32) void viterbi_kernel(
    const float* __restrict__ pot, const float* __restrict__ trans,
    const int* __restrict__ mask,
    float* __restrict__ out_dec, float* __restrict__ out_len)
{
    __shared__ unsigned char bp[TT][KTAG];
    __shared__ unsigned char dec[TT];

    int b = blockIdx.x, k = threadIdx.x;

    float tr[KTAG];
#pragma unroll
    for (int j = 0; j < KTAG; j++) tr[j] = trans[j * KTAG + k];

    const float* pb = pot + (size_t)b * TT * KTAG;
    float s = pb[k];

    for (int t0 = 1; t0 < TT; t0 += 8) {
        float pv[8];
#pragma unroll
        for (int u = 0; u < 8; u++) {
            int t = t0 + u;
            pv[u] = (t < TT) ? pb[(size_t)t * KTAG + k] : 0.f;
        }
#pragma unroll
        for (int u = 0; u < 8; u++) {
            int t = t0 + u;
            if (t >= TT) break;
            float m0 = -INFINITY, m1 = -INFINITY, m2 = -INFINITY, m3 = -INFINITY;
            int i0 = 0, i1 = 1, i2 = 2, i3 = 3;
#pragma unroll
            for (int j = 0; j < KTAG; j += 4) {
                float v0 = __shfl_sync(0xffffffffu, s, j)     + tr[j];
                float v1 = __shfl_sync(0xffffffffu, s, j + 1) + tr[j + 1];
                float v2 = __shfl_sync(0xffffffffu, s, j + 2) + tr[j + 2];
                float v3 = __shfl_sync(0xffffffffu, s, j + 3) + tr[j + 3];
                if (v0 > m0) { m0 = v0; i0 = j; }
                if (v1 > m1) { m1 = v1; i1 = j + 1; }
                if (v2 > m2) { m2 = v2; i2 = j + 2; }
                if (v3 > m3) { m3 = v3; i3 = j + 3; }
            }
            amerge(m0, i0, m1, i1);
            amerge(m2, i2, m3, i3);
            amerge(m0, i0, m2, i2);
            s = m0 + pv[u];
            bp[t][k] = (unsigned char)i0;
        }
    }

    float m0 = -INFINITY, m1 = -INFINITY, m2 = -INFINITY, m3 = -INFINITY;
    int i0 = 0, i1 = 1, i2 = 2, i3 = 3;
#pragma unroll
    for (int j = 0; j < KTAG; j += 4) {
        float v0 = __shfl_sync(0xffffffffu, s, j);
        float v1 = __shfl_sync(0xffffffffu, s, j + 1);
        float v2 = __shfl_sync(0xffffffffu, s, j + 2);
        float v3 = __shfl_sync(0xffffffffu, s, j + 3);
        if (v0 > m0) { m0 = v0; i0 = j; }
        if (v1 > m1) { m1 = v1; i1 = j + 1; }
        if (v2 > m2) { m2 = v2; i2 = j + 2; }
        if (v3 > m3) { m3 = v3; i3 = j + 3; }
    }
    amerge(m0, i0, m1, i1);
    amerge(m2, i2, m3, i3);
    amerge(m0, i0, m2, i2);

    __syncwarp();
    if (k == 0) {
        int tag = i0;
        dec[TT - 1] = (unsigned char)tag;
        for (int t = TT - 2; t >= 0; t--) {
            tag = bp[t + 1][tag];
            dec[t] = (unsigned char)tag;
        }
    }
    __syncwarp();

    for (int t = k; t < TT; t += 32)
        out_dec[(size_t)b * TT + t] = (float)dec[t];

    int sum = 0;
    for (int t = k; t < TT; t += 32) sum += mask[(size_t)b * TT + t];
#pragma unroll
    for (int o = 16; o > 0; o >>= 1) sum += __shfl_down_sync(0xffffffffu, sum, o);
    if (k == 0) out_len[b] = (float)sum;
}

// K5: copy chain_kernel into the output tail (input-independent; launched
// early so proj_mma is the 4th launch and gets profiled)
__global__ void tail_kernel(const float* __restrict__ chain, float* __restrict__ outc)
{
    int i = threadIdx.x + blockIdx.x * blockDim.x;
    if (i < KTAG * KTAG) outc[i] = chain[i];
}

// ---------------------------------------------------------------------------
extern "C" void kernel_launch(void* const* d_in, const int* in_sizes, int n_in,
                              void* d_out, int out_size)
{
    const float* X      = (const float*)d_in[0];
    const int*   mask   = (const int*)d_in[1];
    const float* fwK    = (const float*)d_in[2];
    const float* fwR    = (const float*)d_in[3];
    const float* fwBias = (const float*)d_in[4];
    const float* bwK    = (const float*)d_in[5];
    const float* bwR    = (const float*)d_in[6];
    const float* bwBias = (const float*)d_in[7];
    const float* dK     = (const float*)d_in[8];
    const float* dB     = (const float*)d_in[9];
    const float* chain  = (const float*)d_in[10];
    const float* lb     = (const float*)d_in[11];
    const float* rb     = (const float*)d_in[12];

    float* out       = (float*)d_out;
    float* out_dec   = out;                              // B*T
    float* pot       = out + (size_t)BB * TT;            // B*T*K
    float* out_len   = pot + (size_t)BB * TT * KTAG;     // B
    float* out_chain = out_len + BB;                     // K*K

    cudaFuncSetAttribute(proj_mma, cudaFuncAttributeMaxDynamicSharedMemorySize, SMEM_PROJ);

    prep_x<<<2048, 256>>>(X);
    prep_b<<<NCOMB, 256>>>(fwK, bwK);
    tail_kernel<<<4, 256>>>(chain, out_chain);
    dim3 gp(NCOMB / 128, (BB * TT) / 128);
    proj_mma<<<gp, 256, SMEM_PROJ>>>(fwBias, bwBias);    // 4th launch -> ncu
    dim3 g2(BB / NBAT, 2);
    gru_kernel<<<g2, GH>>>(fwR, bwR, fwBias, bwBias, mask);
    pot_kernel<<<(BB * TT) / PROWS, 256>>>(dK, dB, lb, rb, pot);
    viterbi_kernel<<<BB, 32>>>(pot, chain, mask, out_dec, out_len);
}

// round 10
// speedup vs baseline: 1.1777x; 1.0205x over previous
#include <cuda_runtime.h>
#include <cuda_fp16.h>
#include <math.h>
#include <cstdint>

#define BB 256
#define TT 512
#define DD 256
#define HH 64
#define KTAG 32
#define GH 192      // 3*H
#define NCOMB 384   // fw 192 | bw 192

// Scratch (allocation-free rule: __device__ globals)
__device__ float g_xp[(size_t)BB * TT * NCOMB];      // [b,t, fw(z,r,h)|bw(z,r,h)]
__device__ float g_hidden[(size_t)BB * TT * 2 * HH]; // [b,t, fw64|bw64]
// fp16x2 planes of X [131072][256] and combined transposed weights [384][256]
__device__ unsigned short g_Xh0[(size_t)BB * TT * DD];
__device__ unsigned short g_Xh1[(size_t)BB * TT * DD];
__device__ unsigned short g_Bh0[(size_t)NCOMB * DD];
__device__ unsigned short g_Bh1[(size_t)NCOMB * DD];

// packed fp32x2 helpers
#define FFMA2(acc, a, b) \
    asm("fma.rn.f32x2 %0, %1, %2, %0;" : "+l"(acc) : "l"(a), "l"(b))
#define PACK2(out, lo, hi) \
    asm("mov.b64 %0, {%1, %2};" : "=l"(out) : "r"(__float_as_uint(lo)), "r"(__float_as_uint(hi)))
#define UNPACK2(lo, hi, in) \
    asm("mov.b64 {%0, %1}, %2;" : "=f"(lo), "=f"(hi) : "l"(in))

// fast gate math: MUFU ex2/rcp only, no IEEE div, rel err ~1e-6
__device__ __forceinline__ float fast_sigmoid(float x) {
    float e, r;
    asm("ex2.approx.ftz.f32 %0, %1;" : "=f"(e) : "f"(x * -1.4426950408889634f));
    asm("rcp.approx.ftz.f32 %0, %1;" : "=f"(r) : "f"(1.0f + e));
    return r;
}
__device__ __forceinline__ float fast_tanh(float x) {
    float ax = fabsf(x);
    float e, r;
    asm("ex2.approx.ftz.f32 %0, %1;" : "=f"(e) : "f"(ax * -2.8853900817779268f));
    asm("rcp.approx.ftz.f32 %0, %1;" : "=f"(r) : "f"(1.0f + e));
    float t = (1.0f - e) * r;
    return __uint_as_float(__float_as_uint(t) | (__float_as_uint(x) & 0x80000000u));
}

// fp16 mma m16n8k16 (native HMMA, sm_80+, valid under compute_103)
#define MMA_F16(c, a, b) \
    asm volatile("mma.sync.aligned.m16n8k16.row.col.f32.f16.f16.f32 " \
        "{%0,%1,%2,%3}, {%4,%5,%6,%7}, {%8,%9}, {%0,%1,%2,%3};" \
        : "+f"((c)[0]), "+f"((c)[1]), "+f"((c)[2]), "+f"((c)[3]) \
        : "r"((a)[0]), "r"((a)[1]), "r"((a)[2]), "r"((a)[3]), \
          "r"((b)[0]), "r"((b)[1]))

__device__ __forceinline__ void fp16_split2(float x, unsigned short& h0, unsigned short& h1)
{
    __half a = __float2half_rn(x);
    float f0 = __half2float(a);
    __half b = __float2half_rn(x - f0);
    h0 = __half_as_ushort(a);
    h1 = __half_as_ushort(b);
}

// ---------------------------------------------------------------------------
// K0a: split X into 2 fp16 planes (memory-bound)
// ---------------------------------------------------------------------------
__global__ void prep_x(const float* __restrict__ X)
{
    const size_t N4 = (size_t)BB * TT * DD / 4;
    size_t i = (size_t)blockIdx.x * blockDim.x + threadIdx.x;
    size_t stride = (size_t)gridDim.x * blockDim.x;
    for (size_t p = i; p < N4; p += stride) {
        float4 v = ((const float4*)X)[p];
        float xs[4] = {v.x, v.y, v.z, v.w};
        unsigned short h0[4], h1[4];
#pragma unroll
        for (int e = 0; e < 4; e++) fp16_split2(xs[e], h0[e], h1[e]);
        ((uint2*)g_Xh0)[p] = make_uint2((uint32_t)h0[0] | ((uint32_t)h0[1] << 16),
                                        (uint32_t)h0[2] | ((uint32_t)h0[3] << 16));
        ((uint2*)g_Xh1)[p] = make_uint2((uint32_t)h1[0] | ((uint32_t)h1[1] << 16),
                                        (uint32_t)h1[2] | ((uint32_t)h1[3] << 16));
    }
}

// ---------------------------------------------------------------------------
// K0b: transpose + split the combined input weights: g_Bh[n][k]
// ---------------------------------------------------------------------------
__global__ void prep_b(const float* __restrict__ fwK, const float* __restrict__ bwK)
{
    int n = blockIdx.x;     // 0..383
    int k = threadIdx.x;    // 0..255
    float w = (n < GH) ? fwK[(size_t)k * GH + n] : bwK[(size_t)k * GH + (n - GH)];
    unsigned short h0, h1;
    fp16_split2(w, h0, h1);
    g_Bh0[(size_t)n * DD + k] = h0;
    g_Bh1[(size_t)n * DD + k] = h1;
}

// ---------------------------------------------------------------------------
// K1: proj = X @ Bt^T + bias via fp16x2 3-product mma.sync m16n8k16.
// __launch_bounds__(256,2): cap regs at 128 so 2 CTAs co-reside per SM.
// ---------------------------------------------------------------------------
#define PITCH 20
#define APLANE 2560   // u32 units per plane (128 rows * 20)
#define SM_BIAS 0
#define SM_A 512
#define SM_B (512 + 2 * APLANE * 4)
#define SMEM_PROJ (512 + 4 * APLANE * 4)   // 41472 bytes

__global__ __launch_bounds__(256, 2) void proj_mma(
    const float* __restrict__ fwB, const float* __restrict__ bwB)
{
    extern __shared__ __align__(16) char smem[];
    float* bias_sm = (float*)(smem + SM_BIAS);
    uint32_t* AU = (uint32_t*)(smem + SM_A);
    uint32_t* BU = (uint32_t*)(smem + SM_B);

    const int tid = threadIdx.x;
    const int w = tid >> 5;
    const int lane = tid & 31;
    const int g = lane >> 2;
    const int x = lane & 3;
    const int m_off = (w & 1) * 64;
    const int n_off = (w >> 1) * 32;

    const int n0 = blockIdx.x * 128;   // 0,128,256
    const int m0 = blockIdx.y * 128;

    for (int i = tid; i < 128; i += 256) {
        int n = n0 + i;
        bias_sm[i] = (n < GH) ? fwB[n] : bwB[n - GH];
    }

    float C[4][4][4];
#pragma unroll
    for (int mt = 0; mt < 4; mt++)
#pragma unroll
        for (int nt = 0; nt < 4; nt++)
#pragma unroll
            for (int q = 0; q < 4; q++) C[mt][nt][q] = 0.f;

    int ar0[4], bc0[4];
#pragma unroll
    for (int mt = 0; mt < 4; mt++) ar0[mt] = (m_off + mt * 16 + g) * PITCH;
#pragma unroll
    for (int nt = 0; nt < 4; nt++) bc0[nt] = (n_off + nt * 8 + g) * PITCH;

    const unsigned short* Asrc[2] = {g_Xh0, g_Xh1};
    const unsigned short* Bsrc[2] = {g_Bh0, g_Bh1};

    const int crow = tid >> 2;    // 0..63
    const int cq = tid & 3;       // 0..3

    for (int ks = 0; ks < 8; ks++) {
        const int k0 = ks * 32;
#pragma unroll
        for (int p = 0; p < 2; p++) {
#pragma unroll
            for (int rep = 0; rep < 2; rep++) {
                int r = crow + rep * 64;
                uint4 va = *(const uint4*)(Asrc[p] + (size_t)(m0 + r) * DD + k0 + cq * 8);
                *(uint4*)(AU + p * APLANE + r * PITCH + cq * 4) = va;
                uint4 vb = *(const uint4*)(Bsrc[p] + (size_t)(n0 + r) * DD + k0 + cq * 8);
                *(uint4*)(BU + p * APLANE + r * PITCH + cq * 4) = vb;
            }
        }
        __syncthreads();

#pragma unroll
        for (int s = 0; s < 2; s++) {
            const int ub = s * 8 + x;
            uint32_t bf[2][4][2];
#pragma unroll
            for (int p = 0; p < 2; p++)
#pragma unroll
                for (int nt = 0; nt < 4; nt++) {
                    bf[p][nt][0] = BU[p * APLANE + bc0[nt] + ub];
                    bf[p][nt][1] = BU[p * APLANE + bc0[nt] + ub + 4];
                }
#pragma unroll
            for (int pa = 0; pa < 2; pa++) {
                uint32_t af[4][4];
#pragma unroll
                for (int mt = 0; mt < 4; mt++) {
                    int base = pa * APLANE + ar0[mt] + ub;
                    af[mt][0] = AU[base];
                    af[mt][1] = AU[base + 8 * PITCH];
                    af[mt][2] = AU[base + 4];
                    af[mt][3] = AU[base + 8 * PITCH + 4];
                }
                const int nbp = 2 - pa;
#pragma unroll
                for (int pb = 0; pb < 2; pb++) {
                    if (pb >= nbp) break;
#pragma unroll
                    for (int mt = 0; mt < 4; mt++)
#pragma unroll
                        for (int nt = 0; nt < 4; nt++)
                            MMA_F16(C[mt][nt], af[mt], bf[pb][nt]);
                }
            }
        }
        __syncthreads();
    }

#pragma unroll
    for (int mt = 0; mt < 4; mt++) {
        int r0 = m0 + m_off + mt * 16 + g;
#pragma unroll
        for (int nt = 0; nt < 4; nt++) {
            int col = n_off + nt * 8 + 2 * x;
            float b0 = bias_sm[col], b1 = bias_sm[col + 1];
            float2 v0 = make_float2(C[mt][nt][0] + b0, C[mt][nt][1] + b1);
            float2 v1 = make_float2(C[mt][nt][2] + b0, C[mt][nt][3] + b1);
            *(float2*)(g_xp + (size_t)r0 * NCOMB + n0 + col) = v0;
            *(float2*)(g_xp + (size_t)(r0 + 8) * NCOMB + n0 + col) = v1;
        }
    }
}

// ---------------------------------------------------------------------------
// K2: GRU recurrence. 384 threads: group A (0..191) half-dot over h[0:32]
// (adds recurrent bias to BOTH batch partials), group B (192..383) h[32:64].
// Gate threads (0..63) combine halves. Producers = threads 64..191 (R7 ring).
// ---------------------------------------------------------------------------
#define NBAT 2
#define RS 4

__global__ __launch_bounds__(384) void gru_kernel(
    const float* __restrict__ rec_fw, const float* __restrict__ rec_bw,
    const float* __restrict__ bias_fw, const float* __restrict__ bias_bw,
    const int* __restrict__ mask)
{
    __shared__ __align__(16) float h_sm[NBAT][HH];
    __shared__ float hpA[NBAT][GH];
    __shared__ float hpB[NBAT][GH];
    __shared__ float ring[RS][NBAT][3][HH];
    __shared__ int ringm[RS][NBAT];

    const int dir = blockIdx.y;
    const int b0 = blockIdx.x * NBAT;
    const int tid = threadIdx.x;
    const int grp = (tid >= GH) ? 1 : 0;     // 0: k in [0,32), 1: k in [32,64)
    const int j = grp ? (tid - GH) : tid;    // output column 0..191

    const float* rec = dir ? rec_bw : rec_fw;
    unsigned long long rp[16];
#pragma unroll
    for (int i = 0; i < 16; i++) {
        int row = grp * 32 + 2 * i;
        float r0 = rec[row * GH + j];
        float r1 = rec[(row + 1) * GH + j];
        PACK2(rp[i], r0, r1);
    }
    const float brj = grp ? 0.f : (dir ? bias_bw : bias_fw)[GH + j];

    if (tid < HH) {
#pragma unroll
        for (int nb = 0; nb < NBAT; nb++) h_sm[nb][tid] = 0.f;
    }

    const int is_prod = (tid >= HH && tid < GH);
    const int pid = tid - HH;        // 0..127 when producer
    const int pnb = (pid >> 6) & 1;  // batch 0/1
    const int pjj = pid & 63;

#define LDXP(TF, Z, R, H, M) do { \
        int _ttf = dir ? (TT - 1 - (TF)) : (TF); \
        const float* _xr = g_xp + ((size_t)(b0 + pnb) * TT + _ttf) * NCOMB + dir * GH; \
        Z = _xr[pjj]; R = _xr[HH + pjj]; H = _xr[2 * HH + pjj]; \
        M = mask[(b0 + pnb) * TT + _ttf]; \
    } while (0)

    float s0z = 0, s0r = 0, s0h = 0, s1z = 0, s1r = 0, s1h = 0, s2z = 0, s2r = 0, s2h = 0;
    int s0m = 1, s1m = 1, s2m = 1;

    if (is_prod) {
        for (int f = 0; f < 3; f++) {
            float z, r, h; int m;
            LDXP(f, z, r, h, m);
            ring[f][pnb][0][pjj] = z;
            ring[f][pnb][1][pjj] = r;
            ring[f][pnb][2][pjj] = h;
            if (pjj == 0) ringm[f][pnb] = m;
        }
        LDXP(3, s0z, s0r, s0h, s0m);
        LDXP(4, s1z, s1r, s1h, s1m);
        LDXP(5, s2z, s2r, s2h, s2m);
    }
    __syncthreads();

    int sr = 0;   // consumer slot (step t)
    int sw = 3;   // producer STS slot (step t+3)

    const ulonglong2* h40 = (const ulonglong2*)h_sm[0] + grp * 8;
    const ulonglong2* h41 = (const ulonglong2*)h_sm[1] + grp * 8;

    for (int t = 0; t < TT; t++) {
        unsigned long long a0x = 0ULL, a0y = 0ULL, a1x = 0ULL, a1y = 0ULL;
#pragma unroll
        for (int i = 0; i < 8; i++) {
            ulonglong2 v0 = h40[i];
            ulonglong2 v1 = h41[i];
            FFMA2(a0x, rp[2 * i], v0.x); FFMA2(a0y, rp[2 * i + 1], v0.y);
            FFMA2(a1x, rp[2 * i], v1.x); FFMA2(a1y, rp[2 * i + 1], v1.y);
        }
        {
            float x0, x1, y0, y1;
            float* dst0 = grp ? hpB[0] : hpA[0];
            float* dst1 = grp ? hpB[1] : hpA[1];
            UNPACK2(x0, x1, a0x); UNPACK2(y0, y1, a0y);
            dst0[j] = (x0 + x1) + (y0 + y1) + brj;
            UNPACK2(x0, x1, a1x); UNPACK2(y0, y1, a1y);
            dst1[j] = (x0 + x1) + (y0 + y1) + brj;   // brj=0 for group B
        }
        __syncthreads();

        if (tid < HH) {
            const int tt = dir ? (TT - 1 - t) : t;
#pragma unroll
            for (int nb = 0; nb < NBAT; nb++) {
                float xz = ring[sr][nb][0][tid];
                float xr_ = ring[sr][nb][1][tid];
                float xh = ring[sr][nb][2][tid];
                int m = ringm[sr][nb];
                float hz = hpA[nb][tid]          + hpB[nb][tid];
                float hr = hpA[nb][HH + tid]     + hpB[nb][HH + tid];
                float hc = hpA[nb][2 * HH + tid] + hpB[nb][2 * HH + tid];
                float hprev = h_sm[nb][tid];
                float z = fast_sigmoid(xz + hz);
                float r = fast_sigmoid(xr_ + hr);
                float c = fast_tanh(xh + r * hc);
                float hn = z * hprev + (1.f - z) * c;
                if (m <= 0) hn = hprev;
                h_sm[nb][tid] = hn;
                g_hidden[((size_t)(b0 + nb) * TT + tt) * (2 * HH) + dir * HH + tid] = hn;
            }
        } else if (is_prod) {
            const int tf = t + 3;
            if (tf < TT) {
                ring[sw][pnb][0][pjj] = s0z;
                ring[sw][pnb][1][pjj] = s0r;
                ring[sw][pnb][2][pjj] = s0h;
                if (pjj == 0) ringm[sw][pnb] = s0m;
            }
            s0z = s1z; s0r = s1r; s0h = s1h; s0m = s1m;
            s1z = s2z; s1r = s2r; s1h = s2h; s1m = s2m;
            const int tl = t + 6;
            if (tl < TT) LDXP(tl, s2z, s2r, s2h, s2m);
        }
        __syncthreads();

        sr++; if (sr == RS) sr = 0;
        sw++; if (sw == RS) sw = 0;
    }
#undef LDXP
}

// ---------------------------------------------------------------------------
// K3: potentials (R9 FFMA2 version)
// ---------------------------------------------------------------------------
#define PROWS 16

__global__ __launch_bounds__(256) void pot_kernel(
    const float* __restrict__ dk, const float* __restrict__ db,
    const float* __restrict__ lb, const float* __restrict__ rb,
    float* __restrict__ pot)
{
    __shared__ __align__(16) unsigned long long ds2[2 * HH][KTAG]; // 32KB
    __shared__ __align__(16) float rows_i[2 * HH][PROWS];          // 8KB

    const int tid = threadIdx.x;

    for (int i = tid; i < 2 * HH * KTAG; i += 256) {
        float v = dk[i];
        int h = i >> 5, k = i & 31;
        unsigned long long d;
        PACK2(d, v, v);
        ds2[h][k] = d;
    }

    const size_t row0 = (size_t)blockIdx.x * PROWS;
    {
        int r = tid & 15, hb = (tid >> 4) * 8;
        const float* src = g_hidden + (row0 + r) * (2 * HH) + hb;
        float4 v0 = ((const float4*)src)[0];
        float4 v1 = ((const float4*)src)[1];
        rows_i[hb + 0][r] = v0.x; rows_i[hb + 1][r] = v0.y;
        rows_i[hb + 2][r] = v0.z; rows_i[hb + 3][r] = v0.w;
        rows_i[hb + 4][r] = v1.x; rows_i[hb + 5][r] = v1.y;
        rows_i[hb + 6][r] = v1.z; rows_i[hb + 7][r] = v1.w;
    }
    __syncthreads();

    const int w = tid >> 5, lane = tid & 31;
    float bv = db[lane];
    unsigned long long acc;
    PACK2(acc, bv, bv);
#pragma unroll
    for (int h = 0; h < 2 * HH; h++) {
        unsigned long long hv = *(const unsigned long long*)&rows_i[h][2 * w];
        FFMA2(acc, hv, ds2[h][lane]);
    }
    float o0, o1;
    UNPACK2(o0, o1, acc);

    size_t ra = row0 + 2 * w;
    size_t rb_ = ra + 1;
    int ta = (int)(ra % TT), tb = (int)(rb_ % TT);
    if (ta == 0)      o0 += lb[lane];
    if (ta == TT - 1) o0 += rb[lane];
    if (tb == 0)      o1 += lb[lane];
    if (tb == TT - 1) o1 += rb[lane];
    pot[ra * KTAG + lane] = o0;
    pot[rb_ * KTAG + lane] = o1;
}

// ---------------------------------------------------------------------------
// K4: Viterbi (unchanged)
// ---------------------------------------------------------------------------
__device__ __forceinline__ void amerge(float& mv, int& mi, float v, int i)
{
    if (v > mv || (v == mv && i < mi)) { mv = v; mi = i; }
}

__global__ __launch_bounds__(32) void viterbi_kernel(
    const float* __restrict__ pot, const float* __restrict__ trans,
    const int* __restrict__ mask,
    float* __restrict__ out_dec, float* __restrict__ out_len)
{
    __shared__ unsigned char bp[TT][KTAG];
    __shared__ unsigned char dec[TT];

    int b = blockIdx.x, k = threadIdx.x;

    float tr[KTAG];
#pragma unroll
    for (int j = 0; j < KTAG; j++) tr[j] = trans[j * KTAG + k];

    const float* pb = pot + (size_t)b * TT * KTAG;
    float s = pb[k];

    for (int t0 = 1; t0 < TT; t0 += 8) {
        float pv[8];
#pragma unroll
        for (int u = 0; u < 8; u++) {
            int t = t0 + u;
            pv[u] = (t < TT) ? pb[(size_t)t * KTAG + k] : 0.f;
        }
#pragma unroll
        for (int u = 0; u < 8; u++) {
            int t = t0 + u;
            if (t >= TT) break;
            float m0 = -INFINITY, m1 = -INFINITY, m2 = -INFINITY, m3 = -INFINITY;
            int i0 = 0, i1 = 1, i2 = 2, i3 = 3;
#pragma unroll
            for (int j = 0; j < KTAG; j += 4) {
                float v0 = __shfl_sync(0xffffffffu, s, j)     + tr[j];
                float v1 = __shfl_sync(0xffffffffu, s, j + 1) + tr[j + 1];
                float v2 = __shfl_sync(0xffffffffu, s, j + 2) + tr[j + 2];
                float v3 = __shfl_sync(0xffffffffu, s, j + 3) + tr[j + 3];
                if (v0 > m0) { m0 = v0; i0 = j; }
                if (v1 > m1) { m1 = v1; i1 = j + 1; }
                if (v2 > m2) { m2 = v2; i2 = j + 2; }
                if (v3 > m3) { m3 = v3; i3 = j + 3; }
            }
            amerge(m0, i0, m1, i1);
            amerge(m2, i2, m3, i3);
            amerge(m0, i0, m2, i2);
            s = m0 + pv[u];
            bp[t][k] = (unsigned char)i0;
        }
    }

    float m0 = -INFINITY, m1 = -INFINITY, m2 = -INFINITY, m3 = -INFINITY;
    int i0 = 0, i1 = 1, i2 = 2, i3 = 3;
#pragma unroll
    for (int j = 0; j < KTAG; j += 4) {
        float v0 = __shfl_sync(0xffffffffu, s, j);
        float v1 = __shfl_sync(0xffffffffu, s, j + 1);
        float v2 = __shfl_sync(0xffffffffu, s, j + 2);
        float v3 = __shfl_sync(0xffffffffu, s, j + 3);
        if (v0 > m0) { m0 = v0; i0 = j; }
        if (v1 > m1) { m1 = v1; i1 = j + 1; }
        if (v2 > m2) { m2 = v2; i2 = j + 2; }
        if (v3 > m3) { m3 = v3; i3 = j + 3; }
    }
    amerge(m0, i0, m1, i1);
    amerge(m2, i2, m3, i3);
    amerge(m0, i0, m2, i2);

    __syncwarp();
    if (k == 0) {
        int tag = i0;
        dec[TT - 1] = (unsigned char)tag;
        for (int t = TT - 2; t >= 0; t--) {
            tag = bp[t + 1][tag];
            dec[t] = (unsigned char)tag;
        }
    }
    __syncwarp();

    for (int t = k; t < TT; t += 32)
        out_dec[(size_t)b * TT + t] = (float)dec[t];

    int sum = 0;
    for (int t = k; t < TT; t += 32) sum += mask[(size_t)b * TT + t];
#pragma unroll
    for (int o = 16; o > 0; o >>= 1) sum += __shfl_down_sync(0xffffffffu, sum, o);
    if (k == 0) out_len[b] = (float)sum;
}

// K5: copy chain_kernel into the output tail
__global__ void tail_kernel(const float* __restrict__ chain, float* __restrict__ outc)
{
    int i = threadIdx.x + blockIdx.x * blockDim.x;
    if (i < KTAG * KTAG) outc[i] = chain[i];
}

// ---------------------------------------------------------------------------
extern "C" void kernel_launch(void* const* d_in, const int* in_sizes, int n_in,
                              void* d_out, int out_size)
{
    const float* X      = (const float*)d_in[0];
    const int*   mask   = (const int*)d_in[1];
    const float* fwK    = (const float*)d_in[2];
    const float* fwR    = (const float*)d_in[3];
    const float* fwBias = (const float*)d_in[4];
    const float* bwK    = (const float*)d_in[5];
    const float* bwR    = (const float*)d_in[6];
    const float* bwBias = (const float*)d_in[7];
    const float* dK     = (const float*)d_in[8];
    const float* dB     = (const float*)d_in[9];
    const float* chain  = (const float*)d_in[10];
    const float* lb     = (const float*)d_in[11];
    const float* rb     = (const float*)d_in[12];

    float* out       = (float*)d_out;
    float* out_dec   = out;                              // B*T
    float* pot       = out + (size_t)BB * TT;            // B*T*K
    float* out_len   = pot + (size_t)BB * TT * KTAG;     // B
    float* out_chain = out_len + BB;                     // K*K

    cudaFuncSetAttribute(proj_mma, cudaFuncAttributeMaxDynamicSharedMemorySize, SMEM_PROJ);

    prep_x<<<2048, 256>>>(X);
    prep_b<<<NCOMB, 256>>>(fwK, bwK);
    dim3 gp(NCOMB / 128, (BB * TT) / 128);
    proj_mma<<<gp, 256, SMEM_PROJ>>>(fwBias, bwBias);
    dim3 g2(BB / NBAT, 2);
    gru_kernel<<<g2, 2 * GH>>>(fwR, bwR, fwBias, bwBias, mask);  // 4th -> ncu
    pot_kernel<<<(BB * TT) / PROWS, 256>>>(dK, dB, lb, rb, pot);
    viterbi_kernel<<<BB, 32>>>(pot, chain, mask, out_dec, out_len);
    tail_kernel<<<4, 256>>>(chain, out_chain);
}